// round 13
// baseline (speedup 1.0000x reference)
#include <cuda_runtime.h>

// Fused masked-scale MSE, round 13:
//   R5/R12 winner with ONE change: block geometry 256x2048 -> 512x1024.
//   Same total threads (524288), same per-thread work (16 float4), same
//   regs/RF occupancy (4 CTAs/SM x 512thr = 64 warps/SM). Halves the number
//   of block epilogues (atomics/tickets) and CTA dispatches. Last untested
//   axis; in-band result closes the problem at the R5 config.

__device__ float        g_partial = 0.0f;
__device__ unsigned int g_ticket  = 0u;

__device__ __forceinline__ float elem_term(float n, float l) {
    // labels are exactly 0.0f, 1.0f, or 2.0f
    float sn = (l == 1.0f) ? 10.0f : ((l == 2.0f) ? 5.0f : 1.0f);
    float sl = (l == 0.0f) ? 1.0f : 10.0f;
    float d = fmaf(n, sn, -l * sl);
    return d * d;
}

__global__ void __launch_bounds__(512)
mse_loss_kernel(const float* __restrict__ norms,
                const float* __restrict__ labels,
                float* __restrict__ out,
                int n_vec,      // number of float4 elements
                float inv_n)
{
    const float4* __restrict__ n4 = reinterpret_cast<const float4*>(norms);
    const float4* __restrict__ l4 = reinterpret_cast<const float4*>(labels);

    int idx = blockIdx.x * blockDim.x + threadIdx.x;
    int stride = gridDim.x * blockDim.x;

    float acc = 0.0f;
    // 2x unroll of the grid-stride loop: front-batches 4 float4 loads
    // per iteration for high MLP.  (Measured-best mainloop shape.)
    for (int i = idx; i < n_vec; i += 2 * stride) {
        float4 a0 = n4[i];
        float4 b0 = l4[i];
        int j = i + stride;
        float4 a1, b1;
        bool have2 = (j < n_vec);
        if (have2) { a1 = n4[j]; b1 = l4[j]; }

        acc += elem_term(a0.x, b0.x);
        acc += elem_term(a0.y, b0.y);
        acc += elem_term(a0.z, b0.z);
        acc += elem_term(a0.w, b0.w);
        if (have2) {
            acc += elem_term(a1.x, b1.x);
            acc += elem_term(a1.y, b1.y);
            acc += elem_term(a1.z, b1.z);
            acc += elem_term(a1.w, b1.w);
        }
    }

    // warp reduction
    #pragma unroll
    for (int off = 16; off > 0; off >>= 1)
        acc += __shfl_down_sync(0xffffffffu, acc, off);

    __shared__ float warp_sums[16];
    int lane = threadIdx.x & 31;
    int wid  = threadIdx.x >> 5;
    if (lane == 0) warp_sums[wid] = acc;
    __syncthreads();

    if (wid == 0) {
        float v = (lane < (int)(blockDim.x >> 5)) ? warp_sums[lane] : 0.0f;
        #pragma unroll
        for (int off = 8; off > 0; off >>= 1)
            v += __shfl_down_sync(0xffffffffu, v, off);

        if (lane == 0) {
            atomicAdd(&g_partial, v);
            __threadfence();
            unsigned int ticket = atomicAdd(&g_ticket, 1u);
            if (ticket == gridDim.x - 1) {
                // all block partials visible; finish and reset for next replay
                out[0] = g_partial * inv_n;
                g_partial = 0.0f;
                g_ticket  = 0u;
            }
        }
    }
}

extern "C" void kernel_launch(void* const* d_in, const int* in_sizes, int n_in,
                              void* d_out, int out_size)
{
    const float* norms  = (const float*)d_in[0];
    const float* labels = (const float*)d_in[1];
    float* out = (float*)d_out;

    int n_elems = in_sizes[0];        // 33554432
    int n_vec   = n_elems / 4;        // 8388608
    float inv_n = 1.0f / (float)n_elems;

    const int threads = 512;
    const int blocks  = 1024;         // same total threads as the 256x2048 winner

    mse_loss_kernel<<<blocks, threads>>>(norms, labels, out, n_vec, inv_n);
}

// round 14
// speedup vs baseline: 1.0059x; 1.0059x over previous
#include <cuda_runtime.h>

// Fused masked-scale MSE — FINAL (R5 configuration, best recorded 43.23us).
//
// Closed after a 13-round sweep. Binding constraint: B300 LTS chip throughput
// (~6.3-6.6 TB/s measured plateau on 268MB streamed); all instruction-side
// pipes <30%, MLP saturated 14x over the latency-hiding requirement.
//
// Measured-best choices:
//  - predicated 2x-unroll grid-stride float4 mainloop (beats counted/
//    pointer-carried loops x3, beats __ldcs, ties v8-256bit within noise)
//  - int32 indexing (alu 26% vs 34% for long long)
//  - grid 2048 x 256 (beats 1216 one-wave and 4096; 512x1024 ties)
//  - fused epilogue: warp-shuffle block reduce -> single-address atomicAdd ->
//    last-block ticket writes out and resets scratch (graph-replay safe;
//    saves ~1.3us vs separate zero-init launch; beats 64-slot spread atomics)

__device__ float        g_partial = 0.0f;
__device__ unsigned int g_ticket  = 0u;

__device__ __forceinline__ float elem_term(float n, float l) {
    // labels are exactly 0.0f, 1.0f, or 2.0f
    float sn = (l == 1.0f) ? 10.0f : ((l == 2.0f) ? 5.0f : 1.0f);
    float sl = (l == 0.0f) ? 1.0f : 10.0f;
    float d = fmaf(n, sn, -l * sl);
    return d * d;
}

__global__ void __launch_bounds__(256)
mse_loss_kernel(const float* __restrict__ norms,
                const float* __restrict__ labels,
                float* __restrict__ out,
                int n_vec,      // number of float4 elements
                float inv_n)
{
    const float4* __restrict__ n4 = reinterpret_cast<const float4*>(norms);
    const float4* __restrict__ l4 = reinterpret_cast<const float4*>(labels);

    int idx = blockIdx.x * blockDim.x + threadIdx.x;
    int stride = gridDim.x * blockDim.x;

    float acc = 0.0f;
    // 2x unroll of the grid-stride loop: front-batches 4 float4 loads
    // per iteration for high MLP.
    for (int i = idx; i < n_vec; i += 2 * stride) {
        float4 a0 = n4[i];
        float4 b0 = l4[i];
        int j = i + stride;
        float4 a1, b1;
        bool have2 = (j < n_vec);
        if (have2) { a1 = n4[j]; b1 = l4[j]; }

        acc += elem_term(a0.x, b0.x);
        acc += elem_term(a0.y, b0.y);
        acc += elem_term(a0.z, b0.z);
        acc += elem_term(a0.w, b0.w);
        if (have2) {
            acc += elem_term(a1.x, b1.x);
            acc += elem_term(a1.y, b1.y);
            acc += elem_term(a1.z, b1.z);
            acc += elem_term(a1.w, b1.w);
        }
    }

    // warp reduction
    #pragma unroll
    for (int off = 16; off > 0; off >>= 1)
        acc += __shfl_down_sync(0xffffffffu, acc, off);

    __shared__ float warp_sums[8];
    int lane = threadIdx.x & 31;
    int wid  = threadIdx.x >> 5;
    if (lane == 0) warp_sums[wid] = acc;
    __syncthreads();

    if (wid == 0) {
        float v = (lane < (int)(blockDim.x >> 5)) ? warp_sums[lane] : 0.0f;
        #pragma unroll
        for (int off = 4; off > 0; off >>= 1)
            v += __shfl_down_sync(0xffffffffu, v, off);

        if (lane == 0) {
            atomicAdd(&g_partial, v);
            __threadfence();
            unsigned int ticket = atomicAdd(&g_ticket, 1u);
            if (ticket == gridDim.x - 1) {
                // all block partials visible; finish and reset for next replay
                out[0] = g_partial * inv_n;
                g_partial = 0.0f;
                g_ticket  = 0u;
            }
        }
    }
}

extern "C" void kernel_launch(void* const* d_in, const int* in_sizes, int n_in,
                              void* d_out, int out_size)
{
    const float* norms  = (const float*)d_in[0];
    const float* labels = (const float*)d_in[1];
    float* out = (float*)d_out;

    int n_elems = in_sizes[0];        // 33554432
    int n_vec   = n_elems / 4;        // 8388608
    float inv_n = 1.0f / (float)n_elems;

    const int threads = 256;
    const int blocks  = 2048;

    mse_loss_kernel<<<blocks, threads>>>(norms, labels, out, n_vec, inv_n);
}